// round 15
// baseline (speedup 1.0000x reference)
#include <cuda_runtime.h>
#include <math.h>

#define B    64
#define T    4096
#define DIM  256
#define NLOC 32
#define KS   31
#define PAD  15
#define TPW  32             // rows per warp
#define WPB  8              // warps per block
#define TPB  (TPW * WPB)    // 256 t per block
#define NCH  (T / TPB)      // 16 chunks per batch -> 1024 streaming blocks
#define PREPC 9             // prep chunks per batch (producer rows)
#define FINC  4             // finisher rows per batch

// -------- scratch (static device globals; no allocation allowed) ----------
__device__ float g_u[B * DIM];            // W^T q per batch
__device__ float g_g[B * KS];             // collapsed conv kernel per batch
__device__ float g_cb[B];                 // collapsed conv bias per batch
__device__ float g_energ[B * T];          // raw energies
__device__ float g_pm[B * NCH];           // per-block running max
__device__ float g_ps[B * NCH];           // per-block exp-sum
__device__ float g_pctx[B * NCH * DIM];   // per-block unnormalized context
__device__ int   g_cnt[B];                // per-batch prep arrival counter (0-init)
__device__ int   g_done[B];               // per-batch streaming-chunk counter (0-init)
__device__ int   g_fin[B];                // per-batch finisher counter (0-init)

__device__ __forceinline__ int ld_acquire_gpu(const int* p) {
    int v;
    asm volatile("ld.acquire.gpu.global.b32 %0, [%1];" : "=r"(v) : "l"(p) : "memory");
    return v;
}

// ---------------------------------------------------------------------------
// Fused kernel: grid (B, 29).
//   y in [0,9)    : producer block (batch b, prep chunk y) — lowest bids,
//                   resident in wave 1.
//   y in [9,25)   : streaming block (batch b, chunk y-9); spins on
//                   g_cnt[b]==9 after issuing phase-1 loads; signals g_done.
//   y in [25,29)  : finisher block (batch b, slice y-25); spins on
//                   g_done[b]==16, then combine + context + attn quarter.
// ---------------------------------------------------------------------------
__global__ void __launch_bounds__(256, 4)
fused_kernel(const float* __restrict__ enc,
             const float* __restrict__ mask,
             const float* __restrict__ q,
             const float* __restrict__ Ww,
             const float* __restrict__ Lw,
             const float* __restrict__ convw,
             const float* __restrict__ convb,
             float* __restrict__ out) {
    const int b   = blockIdx.x;
    const int tid = threadIdx.x;

    if (blockIdx.y < PREPC) {
        // ================= producer: prep chunk c for batch b =================
        __shared__ float sq[DIM];
        __shared__ float part[8][32];
        __shared__ float sv[NLOC];

        const int c  = blockIdx.y;
        const int ln = tid & 31;
        const int eg = tid >> 5;

        sq[tid] = q[b * DIM + tid];
        __syncthreads();

        if (c < 8) {
            const float* wp = Ww + (size_t)(eg * 32) * DIM + c * 32 + ln;
            float acc = 0.f;
#pragma unroll
            for (int e = 0; e < 32; e++)
                acc = fmaf(wp[(size_t)e * DIM], sq[eg * 32 + e], acc);
            part[eg][ln] = acc;
            __syncthreads();
            if (tid < 32) {
                float u = part[0][tid];
#pragma unroll
                for (int j = 1; j < 8; j++) u += part[j][tid];
                g_u[b * DIM + c * 32 + tid] = u;
            }
        } else {
            const float* lp = Lw + (size_t)(eg * 32) * NLOC + ln;
            float acc = 0.f;
#pragma unroll
            for (int e = 0; e < 32; e++)
                acc = fmaf(lp[(size_t)e * NLOC], sq[eg * 32 + e], acc);
            part[eg][ln] = acc;
            __syncthreads();
            if (tid < 32) {
                float v = part[0][tid];
#pragma unroll
                for (int j = 1; j < 8; j++) v += part[j][tid];
                sv[tid] = v;
            }
            __syncthreads();
            if (tid < KS) {
                float gg = 0.f;
#pragma unroll
                for (int cc = 0; cc < NLOC; cc++)
                    gg = fmaf(convw[cc * KS + tid], sv[cc], gg);
                g_g[b * KS + tid] = gg;
            }
            if (tid == 0) {
                float cb = 0.f;
#pragma unroll
                for (int cc = 0; cc < NLOC; cc++) cb = fmaf(convb[cc], sv[cc], cb);
                g_cb[b] = cb;
            }
        }

        __threadfence();
        __syncthreads();
        if (tid == 0) atomicAdd(&g_cnt[b], 1);
        return;
    }

    if (blockIdx.y < PREPC + NCH) {
        // ================= streaming block (R10-proven hot loop) ==============
        __shared__ float smask[TPB + 2 * PAD];
        __shared__ float red_m[WPB], red_s[WPB];
        __shared__ __align__(16) float red_ctx[WPB][DIM];

        const int ch = blockIdx.y - PREPC;
        const int w  = tid >> 5;
        const int l  = tid & 31;
        const int t0 = ch * TPB;

        // ---- phase 1: independent of prep outputs ----
        for (int j = tid; j < TPB + 2 * PAD; j += 256) {
            int gt = t0 - PAD + j;
            smask[j] = (gt >= 0 && gt < T) ? mask[b * T + gt] : 0.f;
        }

        const int tw0 = t0 + w * TPW;
        const float* base = enc + ((size_t)tw0 * B + b) * DIM + l * 8;
        const size_t stride = (size_t)B * DIM;

        float4 pf0[2], pf1[2];
        pf0[0] = __ldcs((const float4*)(base));
        pf1[0] = __ldcs((const float4*)(base + 4));
        pf0[1] = __ldcs((const float4*)(base + stride));
        pf1[1] = __ldcs((const float4*)(base + stride + 4));

        // ---- per-batch readiness: all 9 prep chunks arrived ----
        if (tid == 0) {
            while (ld_acquire_gpu(&g_cnt[b]) < PREPC) __nanosleep(32);
        }
        __syncthreads();

        const float4 uA = *(const float4*)(g_u + b * DIM + l * 8);
        const float4 uB = *(const float4*)(g_u + b * DIM + l * 8 + 4);
        const float  gl = (l < KS) ? g_g[b * KS + l] : 0.f;
        const float  cb = g_cb[b];

        float m = -INFINITY, s = 0.f;
        float cx[8] = {0.f, 0.f, 0.f, 0.f, 0.f, 0.f, 0.f, 0.f};

#pragma unroll 4
        for (int i = 0; i < TPW; i++) {
            const int slot = i & 1;
            const float4 a0 = pf0[slot], a1 = pf1[slot];
            if (i + 2 < TPW) {
                const float* np = base + (size_t)(i + 2) * stride;
                pf0[slot] = __ldcs((const float4*)np);
                pf1[slot] = __ldcs((const float4*)(np + 4));
            }
            const float msk = (l < KS) ? smask[w * TPW + i + l] : 0.f;

            float p;
            p = a0.x * uA.x;
            p = fmaf(a0.y, uA.y, p);
            p = fmaf(a0.z, uA.z, p);
            p = fmaf(a0.w, uA.w, p);
            p = fmaf(a1.x, uB.x, p);
            p = fmaf(a1.y, uB.y, p);
            p = fmaf(a1.z, uB.z, p);
            p = fmaf(a1.w, uB.w, p);
            p = fmaf(gl, msk, p);

#pragma unroll
            for (int off = 16; off > 0; off >>= 1)
                p += __shfl_xor_sync(0xffffffffu, p, off);
            p += cb;

            if (l == 0) __stcs(g_energ + b * T + tw0 + i, p);

            if (p > m) {
                const float sc = __expf(m - p);
                s = fmaf(s, sc, 1.f);
#pragma unroll
                for (int j = 0; j < 8; j++) cx[j] *= sc;
                m = p;
                cx[0] += a0.x; cx[1] += a0.y; cx[2] += a0.z; cx[3] += a0.w;
                cx[4] += a1.x; cx[5] += a1.y; cx[6] += a1.z; cx[7] += a1.w;
            } else {
                const float pe = __expf(p - m);
                s += pe;
                cx[0] = fmaf(pe, a0.x, cx[0]); cx[1] = fmaf(pe, a0.y, cx[1]);
                cx[2] = fmaf(pe, a0.z, cx[2]); cx[3] = fmaf(pe, a0.w, cx[3]);
                cx[4] = fmaf(pe, a1.x, cx[4]); cx[5] = fmaf(pe, a1.y, cx[5]);
                cx[6] = fmaf(pe, a1.z, cx[6]); cx[7] = fmaf(pe, a1.w, cx[7]);
            }
        }

        if (l == 0) { red_m[w] = m; red_s[w] = s; }
        *(float4*)(&red_ctx[w][l * 8])     = *(float4*)(&cx[0]);
        *(float4*)(&red_ctx[w][l * 8 + 4]) = *(float4*)(&cx[4]);
        __syncthreads();

        float M = red_m[0];
#pragma unroll
        for (int j = 1; j < WPB; j++) M = fmaxf(M, red_m[j]);
        float S = 0.f, C = 0.f;
#pragma unroll
        for (int j = 0; j < WPB; j++) {
            const float wj = __expf(red_m[j] - M);
            S = fmaf(red_s[j], wj, S);
            C = fmaf(wj, red_ctx[j][tid], C);
        }

        const int pidx = b * NCH + ch;
        g_pctx[pidx * DIM + tid] = C;
        if (tid == 0) { g_pm[pidx] = M; g_ps[pidx] = S; }

        // signal chunk completion for batch b
        __threadfence();
        __syncthreads();
        if (tid == 0) atomicAdd(&g_done[b], 1);
        return;
    }

    // ================= finisher block (batch b, slice sl) =================
    {
        __shared__ float sm[NCH], ss[NCH];
        const int sl = blockIdx.y - (PREPC + NCH);

        if (tid == 0) {
            while (ld_acquire_gpu(&g_done[b]) < NCH) __nanosleep(64);
        }
        __syncthreads();

        if (tid < NCH) { sm[tid] = g_pm[b * NCH + tid]; ss[tid] = g_ps[b * NCH + tid]; }
        __syncthreads();

        float M = sm[0];
#pragma unroll
        for (int j = 1; j < NCH; j++) M = fmaxf(M, sm[j]);
        float S = 0.f;
#pragma unroll
        for (int j = 0; j < NCH; j++) S = fmaf(ss[j], __expf(sm[j] - M), S);
        const float invS = 1.0f / S;

        if (sl == 0) {
            float ctx = 0.f;
#pragma unroll
            for (int j = 0; j < NCH; j++)
                ctx = fmaf(__expf(sm[j] - M), g_pctx[(b * NCH + j) * DIM + tid], ctx);
            out[b * DIM + tid] = ctx * invS;
        }

        const float4* ep = (const float4*)(g_energ + (size_t)b * T) + sl * 256;
        float4*       op = (float4*)(out + (size_t)B * DIM + (size_t)b * T) + sl * 256;
        float4 e = ep[tid];
        float4 r;
        r.x = __expf(e.x - M) * invS;
        r.y = __expf(e.y - M) * invS;
        r.z = __expf(e.z - M) * invS;
        r.w = __expf(e.w - M) * invS;
        op[tid] = r;

        // replay-safe reset: 4th finisher of this batch clears the flags
        __syncthreads();
        if (tid == 0) {
            int v = atomicAdd(&g_fin[b], 1);
            if (v == FINC - 1) {
                g_cnt[b]  = 0;
                g_done[b] = 0;
                g_fin[b]  = 0;
                __threadfence();
            }
        }
    }
}

// ---------------------------------------------------------------------------
extern "C" void kernel_launch(void* const* d_in, const int* in_sizes, int n_in,
                              void* d_out, int out_size) {
    const float* q     = (const float*)d_in[0];
    const float* enc   = (const float*)d_in[1];
    const float* mask  = (const float*)d_in[2];
    const float* Ww    = (const float*)d_in[3];
    const float* Lw    = (const float*)d_in[4];
    const float* convw = (const float*)d_in[5];
    const float* convb = (const float*)d_in[6];
    float* out = (float*)d_out;                  // context(16384) ++ attn(262144)

    dim3 gridF(B, PREPC + NCH + FINC);
    fused_kernel<<<gridF, 256>>>(enc, mask, q, Ww, Lw, convw, convb, out);
}

// round 16
// speedup vs baseline: 1.0440x; 1.0440x over previous
#include <cuda_runtime.h>
#include <math.h>

#define B    64
#define T    4096
#define DIM  256
#define NLOC 32
#define KS   31
#define PAD  15
#define TPW  32             // rows per warp
#define WPB  8              // warps per block
#define TPB  (TPW * WPB)    // 256 t per block
#define NCH  (T / TPB)      // 16 chunks per batch -> 1024 streaming blocks
#define PREPC 9             // prep chunks per batch (producer rows)

// -------- scratch (static device globals; no allocation allowed) ----------
__device__ float g_u[B * DIM];            // W^T q per batch
__device__ float g_g[B * KS];             // collapsed conv kernel per batch
__device__ float g_cb[B];                 // collapsed conv bias per batch
__device__ float g_energ[B * T];          // raw energies (L2-resident)
__device__ float g_pm[B * NCH];           // per-block running max
__device__ float g_ps[B * NCH];           // per-block exp-sum
__device__ float g_pctx[B * NCH * DIM];   // per-block unnormalized context
__device__ int   g_cnt[B];                // per-batch prep arrival counter (0-init)

__device__ __forceinline__ int ld_acquire_gpu(const int* p) {
    int v;
    asm volatile("ld.acquire.gpu.global.b32 %0, [%1];" : "=r"(v) : "l"(p) : "memory");
    return v;
}

// ---------------------------------------------------------------------------
// Fused kernel: grid (B, 25).  (R14-proven structure)
//   y in [0,9)  : producer block (batch b, prep chunk y) — lowest bids.
//   y in [9,25) : streaming block (batch b, chunk y-9); spins on g_cnt[b]==9.
// ---------------------------------------------------------------------------
__global__ void __launch_bounds__(256, 4)
fused_kernel(const float* __restrict__ enc,
             const float* __restrict__ mask,
             const float* __restrict__ q,
             const float* __restrict__ Ww,
             const float* __restrict__ Lw,
             const float* __restrict__ convw,
             const float* __restrict__ convb) {
    const int b   = blockIdx.x;
    const int tid = threadIdx.x;

    if (blockIdx.y < PREPC) {
        // ================= producer: prep chunk c for batch b =================
        __shared__ float sq[DIM];
        __shared__ float part[8][32];
        __shared__ float sv[NLOC];

        const int c  = blockIdx.y;
        const int ln = tid & 31;
        const int eg = tid >> 5;

        sq[tid] = q[b * DIM + tid];
        __syncthreads();

        if (c < 8) {
            const float* wp = Ww + (size_t)(eg * 32) * DIM + c * 32 + ln;
            float acc = 0.f;
#pragma unroll
            for (int e = 0; e < 32; e++)
                acc = fmaf(wp[(size_t)e * DIM], sq[eg * 32 + e], acc);
            part[eg][ln] = acc;
            __syncthreads();
            if (tid < 32) {
                float u = part[0][tid];
#pragma unroll
                for (int j = 1; j < 8; j++) u += part[j][tid];
                g_u[b * DIM + c * 32 + tid] = u;
            }
        } else {
            const float* lp = Lw + (size_t)(eg * 32) * NLOC + ln;
            float acc = 0.f;
#pragma unroll
            for (int e = 0; e < 32; e++)
                acc = fmaf(lp[(size_t)e * NLOC], sq[eg * 32 + e], acc);
            part[eg][ln] = acc;
            __syncthreads();
            if (tid < 32) {
                float v = part[0][tid];
#pragma unroll
                for (int j = 1; j < 8; j++) v += part[j][tid];
                sv[tid] = v;
            }
            __syncthreads();
            if (tid < KS) {
                float gg = 0.f;
#pragma unroll
                for (int cc = 0; cc < NLOC; cc++)
                    gg = fmaf(convw[cc * KS + tid], sv[cc], gg);
                g_g[b * KS + tid] = gg;
            }
            if (tid == 0) {
                float cb = 0.f;
#pragma unroll
                for (int cc = 0; cc < NLOC; cc++) cb = fmaf(convb[cc], sv[cc], cb);
                g_cb[b] = cb;
            }
        }

        __threadfence();
        __syncthreads();
        if (tid == 0) atomicAdd(&g_cnt[b], 1);
        return;
    }

    // ================= streaming block (R10-proven hot loop) =================
    __shared__ float smask[TPB + 2 * PAD];
    __shared__ float red_m[WPB], red_s[WPB];
    __shared__ __align__(16) float red_ctx[WPB][DIM];

    const int ch = blockIdx.y - PREPC;
    const int w  = tid >> 5;
    const int l  = tid & 31;
    const int t0 = ch * TPB;

    // ---- phase 1: independent of prep outputs ----
    for (int j = tid; j < TPB + 2 * PAD; j += 256) {
        int gt = t0 - PAD + j;
        smask[j] = (gt >= 0 && gt < T) ? mask[b * T + gt] : 0.f;
    }

    const int tw0 = t0 + w * TPW;
    const float* base = enc + ((size_t)tw0 * B + b) * DIM + l * 8;
    const size_t stride = (size_t)B * DIM;

    float4 pf0[2], pf1[2];
    pf0[0] = __ldcs((const float4*)(base));
    pf1[0] = __ldcs((const float4*)(base + 4));
    pf0[1] = __ldcs((const float4*)(base + stride));
    pf1[1] = __ldcs((const float4*)(base + stride + 4));

    // ---- per-batch readiness: all 9 prep chunks for batch b arrived ----
    if (tid == 0) {
        while (ld_acquire_gpu(&g_cnt[b]) < PREPC) __nanosleep(32);
    }
    __syncthreads();

    const float4 uA = *(const float4*)(g_u + b * DIM + l * 8);
    const float4 uB = *(const float4*)(g_u + b * DIM + l * 8 + 4);
    const float  gl = (l < KS) ? g_g[b * KS + l] : 0.f;
    const float  cb = g_cb[b];

    float m = -INFINITY, s = 0.f;
    float cx[8] = {0.f, 0.f, 0.f, 0.f, 0.f, 0.f, 0.f, 0.f};

#pragma unroll 4
    for (int i = 0; i < TPW; i++) {
        const int slot = i & 1;
        const float4 a0 = pf0[slot], a1 = pf1[slot];
        if (i + 2 < TPW) {
            const float* np = base + (size_t)(i + 2) * stride;
            pf0[slot] = __ldcs((const float4*)np);
            pf1[slot] = __ldcs((const float4*)(np + 4));
        }
        const float msk = (l < KS) ? smask[w * TPW + i + l] : 0.f;

        float p;
        p = a0.x * uA.x;
        p = fmaf(a0.y, uA.y, p);
        p = fmaf(a0.z, uA.z, p);
        p = fmaf(a0.w, uA.w, p);
        p = fmaf(a1.x, uB.x, p);
        p = fmaf(a1.y, uB.y, p);
        p = fmaf(a1.z, uB.z, p);
        p = fmaf(a1.w, uB.w, p);
        p = fmaf(gl, msk, p);

#pragma unroll
        for (int off = 16; off > 0; off >>= 1)
            p += __shfl_xor_sync(0xffffffffu, p, off);
        p += cb;

        if (l == 0) g_energ[b * T + tw0 + i] = p;   // plain store: stays in L2

        if (p > m) {
            const float sc = __expf(m - p);
            s = fmaf(s, sc, 1.f);
#pragma unroll
            for (int j = 0; j < 8; j++) cx[j] *= sc;
            m = p;
            cx[0] += a0.x; cx[1] += a0.y; cx[2] += a0.z; cx[3] += a0.w;
            cx[4] += a1.x; cx[5] += a1.y; cx[6] += a1.z; cx[7] += a1.w;
        } else {
            const float pe = __expf(p - m);
            s += pe;
            cx[0] = fmaf(pe, a0.x, cx[0]); cx[1] = fmaf(pe, a0.y, cx[1]);
            cx[2] = fmaf(pe, a0.z, cx[2]); cx[3] = fmaf(pe, a0.w, cx[3]);
            cx[4] = fmaf(pe, a1.x, cx[4]); cx[5] = fmaf(pe, a1.y, cx[5]);
            cx[6] = fmaf(pe, a1.z, cx[6]); cx[7] = fmaf(pe, a1.w, cx[7]);
        }
    }

    if (l == 0) { red_m[w] = m; red_s[w] = s; }
    *(float4*)(&red_ctx[w][l * 8])     = *(float4*)(&cx[0]);
    *(float4*)(&red_ctx[w][l * 8 + 4]) = *(float4*)(&cx[4]);
    __syncthreads();

    float M = red_m[0];
#pragma unroll
    for (int j = 1; j < WPB; j++) M = fmaxf(M, red_m[j]);
    float S = 0.f, C = 0.f;
#pragma unroll
    for (int j = 0; j < WPB; j++) {
        const float wj = __expf(red_m[j] - M);
        S = fmaf(red_s[j], wj, S);
        C = fmaf(wj, red_ctx[j][tid], C);
    }

    const int pidx = b * NCH + ch;
    g_pctx[pidx * DIM + tid] = C;                   // plain store: stays in L2
    if (tid == 0) { g_pm[pidx] = M; g_ps[pidx] = S; }
}

// ---------------------------------------------------------------------------
// Kernel C: per-batch combine + context + attn quarter. grid (B, 4). PDL.
// Energy load hoisted above the M/S chain; partials now L2-hot.
// Resets g_cnt for graph-replay determinism.
// ---------------------------------------------------------------------------
__global__ void __launch_bounds__(256)
finish_kernel(float* __restrict__ out) {
    __shared__ float sm[NCH], ss[NCH];
    const int b = blockIdx.x, sl = blockIdx.y, tid = threadIdx.x;

    cudaGridDependencySynchronize();

    // issue the energy load immediately — independent of M/S
    const float4* ep = (const float4*)(g_energ + (size_t)b * T) + sl * 256;
    float4 e = ep[tid];

    if (sl == 0 && tid == 0) g_cnt[b] = 0;   // reset for next replay

    if (tid < NCH) { sm[tid] = g_pm[b * NCH + tid]; ss[tid] = g_ps[b * NCH + tid]; }
    __syncthreads();

    float M = sm[0];
#pragma unroll
    for (int j = 1; j < NCH; j++) M = fmaxf(M, sm[j]);
    float S = 0.f;
#pragma unroll
    for (int j = 0; j < NCH; j++) S = fmaf(ss[j], __expf(sm[j] - M), S);
    const float invS = 1.0f / S;

    if (sl == 0) {
        float ctx = 0.f;
#pragma unroll
        for (int j = 0; j < NCH; j++)
            ctx = fmaf(__expf(sm[j] - M), g_pctx[(b * NCH + j) * DIM + tid], ctx);
        out[b * DIM + tid] = ctx * invS;
    }

    float4* op = (float4*)(out + (size_t)B * DIM + (size_t)b * T) + sl * 256;
    float4 r;
    r.x = __expf(e.x - M) * invS;
    r.y = __expf(e.y - M) * invS;
    r.z = __expf(e.z - M) * invS;
    r.w = __expf(e.w - M) * invS;
    op[tid] = r;
}

// ---------------------------------------------------------------------------
extern "C" void kernel_launch(void* const* d_in, const int* in_sizes, int n_in,
                              void* d_out, int out_size) {
    const float* q     = (const float*)d_in[0];
    const float* enc   = (const float*)d_in[1];
    const float* mask  = (const float*)d_in[2];
    const float* Ww    = (const float*)d_in[3];
    const float* Lw    = (const float*)d_in[4];
    const float* convw = (const float*)d_in[5];
    const float* convb = (const float*)d_in[6];
    float* out = (float*)d_out;                  // context(16384) ++ attn(262144)

    dim3 gridF(B, PREPC + NCH);
    fused_kernel<<<gridF, 256>>>(enc, mask, q, Ww, Lw, convw, convb);

    // finish with PDL behind the fused kernel
    cudaLaunchAttribute attrs[1];
    attrs[0].id = cudaLaunchAttributeProgrammaticStreamSerialization;
    attrs[0].val.programmaticStreamSerializationAllowed = 1;
    cudaLaunchConfig_t cfgC = {};
    cfgC.gridDim  = dim3(B, 4);
    cfgC.blockDim = dim3(256);
    cfgC.attrs = attrs;
    cfgC.numAttrs = 1;
    cudaLaunchKernelEx(&cfgC, finish_kernel, out);
}